// round 15
// baseline (speedup 1.0000x reference)
#include <cuda_runtime.h>
#include <math.h>
#include <stdint.h>

// Problem dims
#define BB 32
#define SS 2048
#define II 128
#define HH 512
#define OO 128

#define RGRID 128        // 8 groups x 16 CTAs

// packed f32x2 FMA (FFMA2) — only reachable via PTX
#define FMA2(acc, a, b) \
    asm("fma.rn.f32x2 %0, %1, %2, %0;" : "+l"(acc) : "l"(a), "l"(b))
#define PACK2(d, s) \
    asm("mov.b64 %0, {%1, %1};" : "=l"(d) : "f"(s))

// ---------------- static device scratch ----------------
__device__ float g_Abuf[SS * BB * 1536];  // x-projections [t][b][z|r|g]
__device__ float g_H0[SS * BB * HH];
__device__ float g_H1[SS * BB * HH];
__device__ float g_zrP[8][16][2][4][512]; // partial z/r pre-acts per writer rank
__device__ float g_gP[8][16][4][512];     // partial g pre-acts per writer rank
__device__ unsigned g_gbar[16 * 32];      // 8 groups x 2 pair-counters (128B apart)

// ---------------- per-group pair barrier (16 arrivals) ----------------
__device__ __forceinline__ void grp_arrive(unsigned* bar) {
    asm volatile("red.release.gpu.global.add.u32 [%0], %1;"
                 :: "l"(bar), "r"(1u) : "memory");
}
__device__ __forceinline__ void grp_wait(unsigned* bar, unsigned tgt) {
    unsigned v;
    do {
        asm volatile("ld.acquire.gpu.global.u32 %0, [%1];"
                     : "=r"(v) : "l"(bar) : "memory");
    } while (v < tgt);
}

__global__ void reset_bar_kernel() {
    int i = threadIdx.x;
    if (i < 16) g_gbar[i * 32] = 0;
}

// ---------------- SGEMM (plain FFMA, known-best) ----------------
__global__ __launch_bounds__(256, 2) void sgemm_kernel(
    const float* __restrict__ A, int amode, int K,
    const float* __restrict__ W0g, const float* __restrict__ W1g, const float* __restrict__ W2g,
    const float* __restrict__ b0g, const float* __restrict__ b1g, const float* __restrict__ b2g,
    int ngate, float* __restrict__ C, int omode, int ldc)
{
    __shared__ float As[8][128];
    __shared__ float Bs[8][132];

    const int tid = threadIdx.x;
    const int bm = blockIdx.x;
    const int ncol0 = blockIdx.y * 128;
    const int gate = ncol0 / ngate;
    const float* W    = (gate == 0) ? W0g : (gate == 1) ? W1g : W2g;
    const float* bias = (gate == 0) ? b0g : (gate == 1) ? b1g : b2g;
    const int ng_off = ncol0 - gate * ngate;

    const int tx = tid & 15;
    const int ty = tid >> 4;

    float acc[8][8];
#pragma unroll
    for (int i = 0; i < 8; i++)
#pragma unroll
        for (int j = 0; j < 8; j++) acc[i][j] = 0.f;

    const int arow = tid >> 1;
    const int ak = (tid & 1) * 4;
    const int grow = bm * 128 + arow;
    long aoff;
    if (amode == 0) aoff = (long)(grow & 31) * (SS * II) + (long)(grow >> 5) * II;
    else            aoff = (long)grow * K;

    const int bk = tid >> 5;
    const int bn = (tid & 31) * 4;

    for (int kk = 0; kk < K; kk += 8) {
        float4 av = *(const float4*)(A + aoff + (kk + ak));
        As[ak + 0][arow] = av.x;
        As[ak + 1][arow] = av.y;
        As[ak + 2][arow] = av.z;
        As[ak + 3][arow] = av.w;
        float4 wv = *(const float4*)(W + (long)(kk + bk) * ngate + (ng_off + bn));
        *(float4*)&Bs[bk][bn] = wv;
        __syncthreads();
#pragma unroll
        for (int k = 0; k < 8; k++) {
            float rm[8], rn[8];
            *(float4*)&rm[0] = *(const float4*)&As[k][ty * 8];
            *(float4*)&rm[4] = *(const float4*)&As[k][ty * 8 + 4];
            *(float4*)&rn[0] = *(const float4*)&Bs[k][tx * 8];
            *(float4*)&rn[4] = *(const float4*)&Bs[k][tx * 8 + 4];
#pragma unroll
            for (int i = 0; i < 8; i++)
#pragma unroll
                for (int j = 0; j < 8; j++)
                    acc[i][j] += rm[i] * rn[j];
        }
        __syncthreads();
    }

#pragma unroll
    for (int i = 0; i < 8; i++) {
        int row = bm * 128 + ty * 8 + i;
        long obase;
        if (omode == 0) obase = (long)row * ldc + ncol0;
        else            obase = (long)(row & 31) * (SS * OO) + (long)(row >> 5) * OO + ncol0;
#pragma unroll
        for (int j = 0; j < 8; j++)
            C[obase + tx * 8 + j] = acc[i][j] + bias[ng_off + tx * 8 + j];
    }
}

// ---------------- partial-sum GRU recurrence, batch-pair pipelined ----------------
// Group = 16 CTAs = 4 batches (pairs P0={b0,b0+1}, P1={b0+2,b0+3}); rank owns
// 32 cols (= 32 k-rows). Only partial sums cross CTAs. The two pairs run half a
// phase apart: every barrier wait has the other pair's dot between its arrive
// and its wait, hiding the round-trip. 2 counters per group, 16 arrivals each.
__global__ void __launch_bounds__(256, 1) gru_part_kernel(
    const float* __restrict__ Abuf,
    const float* __restrict__ Whz, const float* __restrict__ Whr, const float* __restrict__ Whg,
    const float* __restrict__ h0, int layer, float* __restrict__ Hout)
{
    extern __shared__ float smf[];
    float* wz = smf;             // [32 k][512 c'] row slices
    float* wr = wz + 16384;
    float* wg = wr + 16384;
    unsigned long long* hdup  = (unsigned long long*)(wg + 16384); // [32 k][4 b] {h,h}
    unsigned long long* rhdup = hdup + 128;                        // [32 k][4 b] {rh,rh}
    float* hO  = (float*)(rhdup + 128);   // [4 b][32 c] own h
    float* z_s = hO + 128;                // [4 b][32 c]

    const int tid = threadIdx.x;
    const int cta = blockIdx.x;
    const int gid = cta >> 4, rank = cta & 15;
    const int c0 = rank * 32;             // owned cols == owned k-rows
    const int b0 = gid * 4;
    const int ct = tid;                   // owned c'-pair (2ct, 2ct+1)
    // zr finalize mapping (tid<128): gate, batch-within-pair, col
    const int rg = tid >> 6, rb2 = (tid >> 5) & 1, rc = tid & 31;
    // g finalize mapping (tid<64): batch-within-pair = tid>>5, col = tid&31

    // ---- stage weight ROWS k in [c0, c0+32), all 512 cols ----
    for (int idx = tid; idx < 3 * 16384; idx += 256) {
        int m = idx >> 14, rem = idx & 16383;
        int k = rem >> 9, c = rem & 511;
        const float* Wm = (m == 0) ? Whz : (m == 1) ? Whr : Whg;
        smf[m * 16384 + rem] = Wm[(c0 + k) * 512 + c];
    }
    // ---- init own h (tid<128: b=tid>>5, c=tid&31) ----
    if (tid < 128) {
        int b = tid >> 5, c = tid & 31;
        float h = h0[(b0 + b) * 1024 + layer * 512 + c0 + c];
        hO[b * 32 + c] = h;
        unsigned long long hd; PACK2(hd, h);
        hdup[c * 4 + b] = hd;
    }
    __syncthreads();

    unsigned* bar0 = &g_gbar[(gid * 2 + 0) * 32];
    unsigned* bar1 = &g_gbar[(gid * 2 + 1) * 32];
    unsigned ep0 = 0, ep1 = 0;

    const unsigned long long* wz2 = (const unsigned long long*)wz;
    const unsigned long long* wr2 = (const unsigned long long*)wr;
    const unsigned long long* wg2 = (const unsigned long long*)wg;

    float* zrW = &g_zrP[gid][rank][0][0][0];          // gate stride 4*512, b stride 512
    float* gW  = &g_gP[gid][rank][0][0];              // b stride 512
    const float* zrR = &g_zrP[gid][0][rg][0][c0 + rc];    // + b*512, rank stride 4096
    const float* gR  = &g_gP[gid][0][0][c0 + (tid & 31)]; // + b*512, rank stride 2048

    // t=0 Abuf prefetch (both pairs)
    float pA[2] = {0.f, 0.f}, pG[2] = {0.f, 0.f};
    if (tid < 128) {
#pragma unroll
        for (int p = 0; p < 2; p++) {
            const float* ab = Abuf + (size_t)(b0 + 2 * p + rb2) * 1536;
            pA[p] = __ldg(ab + rg * 512 + c0 + rc);
            if (tid < 64) pG[p] = __ldg(ab + 1024 + c0 + (tid & 31)); // rb2==tid>>5
        }
    }

    for (int t = 0; t < SS; t++) {
        // ===== stage 1: dotZR(P0) =====
#pragma unroll
        for (int p = 0; p < 2; p++) {
            // (unrolled manually below via p loop with interleaved barriers)
            unsigned long long az[2] = {0, 0}, ar[2] = {0, 0};
#pragma unroll
            for (int k = 0; k < 32; k++) {
                unsigned long long wzv = wz2[k * 256 + ct];
                unsigned long long wrv = wr2[k * 256 + ct];
                ulonglong2 hp = *(const ulonglong2*)&hdup[k * 4 + 2 * p];
                FMA2(az[0], hp.x, wzv); FMA2(ar[0], hp.x, wrv);
                FMA2(az[1], hp.y, wzv); FMA2(ar[1], hp.y, wrv);
            }
#pragma unroll
            for (int b2 = 0; b2 < 2; b2++) {
                __stcg((double*)(zrW + (2 * p + b2) * 512) + ct,
                       __longlong_as_double(az[b2]));
                __stcg((double*)(zrW + (4 + 2 * p + b2) * 512) + ct,
                       __longlong_as_double(ar[b2]));
            }
            __syncthreads();
            if (tid == 0) grp_arrive(p ? bar1 : bar0);
        }
        ep0++; ep1++;

        // ===== finalize ZR + dotG, P0 then P1 =====
#pragma unroll
        for (int p = 0; p < 2; p++) {
            if (tid == 0) grp_wait(p ? bar1 : bar0, (p ? ep1 : ep0) * 16);
            __syncthreads();
            if (tid < 128) {
                int b = 2 * p + rb2;
                float s = pA[p];
                const float* zp = zrR + b * 512;
#pragma unroll
                for (int w = 0; w < 16; w++) s += __ldcg(zp + w * 4096);
                float sg = 1.f / (1.f + __expf(-s));
                if (rg == 0) {
                    z_s[b * 32 + rc] = sg;
                } else {
                    float rh = sg * hO[b * 32 + rc];
                    unsigned long long rd; PACK2(rd, rh);
                    rhdup[rc * 4 + b] = rd;
                }
            }
            __syncthreads();
            // dotG(p)
            {
                unsigned long long ag[2] = {0, 0};
#pragma unroll
                for (int k = 0; k < 32; k++) {
                    unsigned long long wgv = wg2[k * 256 + ct];
                    ulonglong2 rp = *(const ulonglong2*)&rhdup[k * 4 + 2 * p];
                    FMA2(ag[0], rp.x, wgv);
                    FMA2(ag[1], rp.y, wgv);
                }
#pragma unroll
                for (int b2 = 0; b2 < 2; b2++)
                    __stcg((double*)(gW + (2 * p + b2) * 512) + ct,
                           __longlong_as_double(ag[b2]));
            }
            __syncthreads();
            if (tid == 0) grp_arrive(p ? bar1 : bar0);
        }
        ep0++; ep1++;

        // ---- shadow of wait(bar0): next step's Abuf prefetch ----
        float npA[2] = {0.f, 0.f}, npG[2] = {0.f, 0.f};
        if (t + 1 < SS && tid < 128) {
#pragma unroll
            for (int p = 0; p < 2; p++) {
                const float* ab = Abuf + (size_t)((t + 1) * 32 + b0 + 2 * p + rb2) * 1536;
                npA[p] = __ldg(ab + rg * 512 + c0 + rc);
                if (tid < 64) npG[p] = __ldg(ab + 1024 + c0 + (tid & 31));
            }
        }

        // ===== finalize G + h update, P0 then P1 =====
#pragma unroll
        for (int p = 0; p < 2; p++) {
            if (tid == 0) grp_wait(p ? bar1 : bar0, (p ? ep1 : ep0) * 16);
            __syncthreads();
            if (tid < 64) {
                int b = 2 * p + (tid >> 5), c = tid & 31;
                float s = pG[p];
                const float* gp = gR + b * 512;
#pragma unroll
                for (int w = 0; w < 16; w++) s += __ldcg(gp + w * 2048);
                float g = tanhf(s);
                float z = z_s[b * 32 + c];
                float ho = hO[b * 32 + c];
                float hn = z * ho + (1.f - z) * g;
                hO[b * 32 + c] = hn;
                unsigned long long hd; PACK2(hd, hn);
                hdup[c * 4 + b] = hd;
                Hout[(size_t)(t * 32 + b0 + b) * 512 + c0 + c] = hn;
            }
        }
        pA[0] = npA[0]; pA[1] = npA[1];
        pG[0] = npG[0]; pG[1] = npG[1];
        __syncthreads();
    }
}

// ---------------- hidden-state tail (h at t = SS-1 from Hout) ----------------
__global__ void copy_hidden_kernel(float* __restrict__ out,
                                   const float* __restrict__ H0f,
                                   const float* __restrict__ H1f) {
    int i = blockIdx.x * 256 + threadIdx.x;   // (B, L, H)
    if (i < BB * 2 * HH) {
        int b = i >> 10, rem = i & 1023;
        int l = rem >> 9, h = rem & 511;
        const float* src = l ? H1f : H0f;
        out[i] = src[(size_t)((SS - 1) * 32 + b) * 512 + h];
    }
}

// ---------------- launch ----------------
extern "C" void kernel_launch(void* const* d_in, const int* in_sizes, int n_in,
                              void* d_out, int out_size)
{
    const float* x    = (const float*)d_in[0];
    const float* h0   = (const float*)d_in[1];
    const float* W0xz = (const float*)d_in[2];
    const float* W0hz = (const float*)d_in[3];
    const float* b0z  = (const float*)d_in[4];
    const float* W0xr = (const float*)d_in[5];
    const float* W0hr = (const float*)d_in[6];
    const float* b0r  = (const float*)d_in[7];
    const float* W0xg = (const float*)d_in[8];
    const float* W0hg = (const float*)d_in[9];
    const float* b0g  = (const float*)d_in[10];
    const float* W1xz = (const float*)d_in[11];
    const float* W1hz = (const float*)d_in[12];
    const float* b1z  = (const float*)d_in[13];
    const float* W1xr = (const float*)d_in[14];
    const float* W1hr = (const float*)d_in[15];
    const float* b1r  = (const float*)d_in[16];
    const float* W1xg = (const float*)d_in[17];
    const float* W1hg = (const float*)d_in[18];
    const float* b1g  = (const float*)d_in[19];
    const float* Wy   = (const float*)d_in[20];
    const float* by   = (const float*)d_in[21];
    float* out = (float*)d_out;

    float *Abuf, *H0, *H1;
    cudaGetSymbolAddress((void**)&Abuf, g_Abuf);
    cudaGetSymbolAddress((void**)&H0,   g_H0);
    cudaGetSymbolAddress((void**)&H1,   g_H1);

    // smem: 3*16384 weights + hdup 256 + rhdup 256 + hO 128 + z 128 floats
    const size_t smem = (size_t)(3 * 16384 + 256 + 256 + 128 + 128) * sizeof(float);
    cudaFuncSetAttribute(gru_part_kernel,
                         cudaFuncAttributeMaxDynamicSharedMemorySize, (int)smem);

    dim3 gproj(512, 12);  // M=65536/128, N=1536/128

    // layer 0
    sgemm_kernel<<<gproj, 256>>>(x, 0, II, W0xz, W0xr, W0xg, b0z, b0r, b0g,
                                 512, Abuf, 0, 1536);
    reset_bar_kernel<<<1, 32>>>();
    gru_part_kernel<<<RGRID, 256, smem>>>(Abuf, W0hz, W0hr, W0hg, h0, 0, H0);

    // layer 1
    sgemm_kernel<<<gproj, 256>>>(H0, 1, HH, W1xz, W1xr, W1xg, b1z, b1r, b1g,
                                 512, Abuf, 0, 1536);
    reset_bar_kernel<<<1, 32>>>();
    gru_part_kernel<<<RGRID, 256, smem>>>(Abuf, W1hz, W1hr, W1hg, h0, 1, H1);

    // output head
    dim3 ghead(512, 1);
    sgemm_kernel<<<ghead, 256>>>(H1, 1, HH, Wy, Wy, Wy, by, by, by,
                                 128, out, 1, 0);

    if (out_size >= BB * SS * OO + BB * 2 * HH) {
        copy_hidden_kernel<<<128, 256>>>(out + BB * SS * OO, H0, H1);
    }
}

// round 16
// speedup vs baseline: 1.3418x; 1.3418x over previous
#include <cuda_runtime.h>
#include <math.h>
#include <stdint.h>

// Problem dims
#define BB 32
#define SS 2048
#define II 128
#define HH 512
#define OO 128

#define RGRID 128        // 8 groups x 16 CTAs

// packed f32x2 FMA (FFMA2) — only reachable via PTX
#define FMA2(acc, a, b) \
    asm("fma.rn.f32x2 %0, %1, %2, %0;" : "+l"(acc) : "l"(a), "l"(b))
#define PACK2(d, s) \
    asm("mov.b64 %0, {%1, %1};" : "=l"(d) : "f"(s))

// ---------------- static device scratch ----------------
__device__ float g_Abuf[SS * BB * 1536];  // x-projections [t][b][z|r|g]
__device__ float g_H0[SS * BB * HH];
__device__ float g_H1[SS * BB * HH];
__device__ float g_zrP[8][16][2][4][512]; // partial z/r pre-acts per writer rank
__device__ float g_gP[8][16][4][512];     // partial g pre-acts per writer rank
__device__ unsigned g_gbar[8 * 32];       // per-group barrier counters (128B apart)

// ---------------- per-group barrier (16 arrivals) ----------------
__device__ __forceinline__ void grp_arrive(unsigned* bar) {
    asm volatile("red.release.gpu.global.add.u32 [%0], %1;"
                 :: "l"(bar), "r"(1u) : "memory");
}
__device__ __forceinline__ void grp_wait(unsigned* bar, unsigned tgt) {
    unsigned v;
    do {
        asm volatile("ld.acquire.gpu.global.u32 %0, [%1];"
                     : "=r"(v) : "l"(bar) : "memory");
    } while (v < tgt);
}

__global__ void reset_bar_kernel() {
    int i = threadIdx.x;
    if (i < 8) g_gbar[i * 32] = 0;
}

// ---------------- SGEMM: plain FFMA + register double-buffered staging ----------------
__global__ __launch_bounds__(256, 2) void sgemm_kernel(
    const float* __restrict__ A, int amode, int K,
    const float* __restrict__ W0g, const float* __restrict__ W1g, const float* __restrict__ W2g,
    const float* __restrict__ b0g, const float* __restrict__ b1g, const float* __restrict__ b2g,
    int ngate, float* __restrict__ C, int omode, int ldc)
{
    __shared__ float As[8][128];
    __shared__ float Bs[8][132];

    const int tid = threadIdx.x;
    const int bm = blockIdx.x;
    const int ncol0 = blockIdx.y * 128;
    const int gate = ncol0 / ngate;
    const float* W    = (gate == 0) ? W0g : (gate == 1) ? W1g : W2g;
    const float* bias = (gate == 0) ? b0g : (gate == 1) ? b1g : b2g;
    const int ng_off = ncol0 - gate * ngate;

    const int tx = tid & 15;
    const int ty = tid >> 4;

    float acc[8][8];
#pragma unroll
    for (int i = 0; i < 8; i++)
#pragma unroll
        for (int j = 0; j < 8; j++) acc[i][j] = 0.f;

    const int arow = tid >> 1;
    const int ak = (tid & 1) * 4;
    const int grow = bm * 128 + arow;
    long aoff;
    if (amode == 0) aoff = (long)(grow & 31) * (SS * II) + (long)(grow >> 5) * II;
    else            aoff = (long)grow * K;

    const int bk = tid >> 5;
    const int bn = (tid & 31) * 4;

    // prologue: load tile 0 into registers
    float4 av = *(const float4*)(A + aoff + ak);
    float4 wv = *(const float4*)(W + (long)bk * ngate + (ng_off + bn));

    for (int kk = 0; kk < K; kk += 8) {
        // store current tile to SMEM
        As[ak + 0][arow] = av.x;
        As[ak + 1][arow] = av.y;
        As[ak + 2][arow] = av.z;
        As[ak + 3][arow] = av.w;
        *(float4*)&Bs[bk][bn] = wv;
        __syncthreads();

        // issue next tile's loads NOW (latency hidden under compute below)
        if (kk + 8 < K) {
            av = *(const float4*)(A + aoff + (kk + 8 + ak));
            wv = *(const float4*)(W + (long)(kk + 8 + bk) * ngate + (ng_off + bn));
        }

#pragma unroll
        for (int k = 0; k < 8; k++) {
            float rm[8], rn[8];
            *(float4*)&rm[0] = *(const float4*)&As[k][ty * 8];
            *(float4*)&rm[4] = *(const float4*)&As[k][ty * 8 + 4];
            *(float4*)&rn[0] = *(const float4*)&Bs[k][tx * 8];
            *(float4*)&rn[4] = *(const float4*)&Bs[k][tx * 8 + 4];
#pragma unroll
            for (int i = 0; i < 8; i++)
#pragma unroll
                for (int j = 0; j < 8; j++)
                    acc[i][j] += rm[i] * rn[j];
        }
        __syncthreads();
    }

#pragma unroll
    for (int i = 0; i < 8; i++) {
        int row = bm * 128 + ty * 8 + i;
        long obase;
        if (omode == 0) obase = (long)row * ldc + ncol0;
        else            obase = (long)(row & 31) * (SS * OO) + (long)(row >> 5) * OO + ncol0;
#pragma unroll
        for (int j = 0; j < 8; j++)
            C[obase + tx * 8 + j] = acc[i][j] + bias[ng_off + tx * 8 + j];
    }
}

// ---------------- partial-sum GRU recurrence (EXACT R12 winner) ----------------
// Group = 16 CTAs = 4 batches; CTA rank owns h-columns [32r, 32r+32) — which
// are exactly the k-rows it needs to compute partial pre-activations for ALL
// 512 output columns. No operand exchange: only partial sums cross CTAs
// (fixed per-writer slots, no atomics, deterministic). 2 barriers/step.
__global__ void __launch_bounds__(256, 1) gru_part_kernel(
    const float* __restrict__ Abuf,
    const float* __restrict__ Whz, const float* __restrict__ Whr, const float* __restrict__ Whg,
    const float* __restrict__ h0, int layer, float* __restrict__ Hout)
{
    extern __shared__ float smf[];
    float* wz = smf;             // [32 k][512 c'] row slices
    float* wr = wz + 16384;
    float* wg = wr + 16384;
    unsigned long long* hdup  = (unsigned long long*)(wg + 16384); // [32 k][4 b] {h,h}
    unsigned long long* rhdup = hdup + 128;                        // [32 k][4 b] {rh,rh}
    float* hO  = (float*)(rhdup + 128);   // [4 b][32 c] own h
    float* z_s = hO + 128;                // [4 b][32 c]

    const int tid = threadIdx.x;
    const int cta = blockIdx.x;
    const int gid = cta >> 4, rank = cta & 15;
    const int c0 = rank * 32;             // owned cols == owned k-rows
    const int b0 = gid * 4;
    const int ct = tid;                   // owned c'-pair (2ct, 2ct+1)
    // reader mapping (256 threads = 2 gates x 4 b x 32 c; tid<128 => gate z)
    const int rg = tid >> 7, rb = (tid >> 5) & 3, rc = tid & 31;

    // ---- stage weight ROWS k in [c0, c0+32), all 512 cols ----
    for (int idx = tid; idx < 3 * 16384; idx += 256) {
        int m = idx >> 14, rem = idx & 16383;
        int k = rem >> 9, c = rem & 511;
        const float* Wm = (m == 0) ? Whz : (m == 1) ? Whr : Whg;
        smf[m * 16384 + rem] = Wm[(c0 + k) * 512 + c];
    }
    // ---- init own h ----
    if (tid < 128) {
        float h = h0[(b0 + rb) * 1024 + layer * 512 + c0 + rc];
        hO[tid] = h;
        unsigned long long hd; PACK2(hd, h);
        hdup[rc * 4 + rb] = hd;
    }
    __syncthreads();

    unsigned* bar = &g_gbar[gid * 32];
    unsigned ep = 0;

    const unsigned long long* wz2 = (const unsigned long long*)wz;
    const unsigned long long* wr2 = (const unsigned long long*)wr;
    const unsigned long long* wg2 = (const unsigned long long*)wg;

    float* zrW = &g_zrP[gid][rank][0][0][0];
    float* gW  = &g_gP[gid][rank][0][0];
    const float* zrR = &g_zrP[gid][0][rg][rb][c0 + rc];
    const float* gR  = &g_gP[gid][0][(tid >> 5) & 3][c0 + (tid & 31)];

    // t=0 Abuf prefetch
    float pA, pG = 0.f;
    {
        const float* ab = Abuf + (size_t)(b0 + rb) * 1536;
        pA = __ldg(ab + rg * 512 + c0 + rc);
        if (tid < 128) pG = __ldg(ab + 1024 + c0 + rc);
    }

    for (int t = 0; t < SS; t++) {
        // ---- ZR partial dot: my 32 k-rows -> all 512 c' (pairs), 4 b, 2 gates ----
        {
            unsigned long long az[4] = {0,0,0,0}, ar[4] = {0,0,0,0};
#pragma unroll
            for (int k = 0; k < 32; k++) {
                unsigned long long wzv = wz2[k * 256 + ct];
                unsigned long long wrv = wr2[k * 256 + ct];
                ulonglong2 h01 = *(const ulonglong2*)&hdup[k * 4];
                ulonglong2 h23 = *(const ulonglong2*)&hdup[k * 4 + 2];
                FMA2(az[0], h01.x, wzv); FMA2(ar[0], h01.x, wrv);
                FMA2(az[1], h01.y, wzv); FMA2(ar[1], h01.y, wrv);
                FMA2(az[2], h23.x, wzv); FMA2(ar[2], h23.x, wrv);
                FMA2(az[3], h23.y, wzv); FMA2(ar[3], h23.y, wrv);
            }
#pragma unroll
            for (int b = 0; b < 4; b++) {
                __stcg((double*)(zrW + b * 512) + ct,       __longlong_as_double(az[b]));
                __stcg((double*)(zrW + (4 + b) * 512) + ct, __longlong_as_double(ar[b]));
            }
        }
        __syncthreads();
        if (tid == 0) grp_arrive(bar);
        ep++;
        if (tid == 0) grp_wait(bar, ep * 16);
        __syncthreads();

        // ---- read zr partials (MLP 16) + activations ----
        {
            float s = pA;
#pragma unroll
            for (int w = 0; w < 16; w++) s += __ldcg(zrR + w * 4096);
            float sg = 1.f / (1.f + __expf(-s));
            if (rg == 0) {
                z_s[tid] = sg;
            } else {
                float rh = sg * hO[rb * 32 + rc];
                unsigned long long rd; PACK2(rd, rh);
                rhdup[rc * 4 + rb] = rd;
            }
        }
        __syncthreads();

        // ---- G partial dot ----
        {
            unsigned long long ag[4] = {0,0,0,0};
#pragma unroll
            for (int k = 0; k < 32; k++) {
                unsigned long long wgv = wg2[k * 256 + ct];
                ulonglong2 r01 = *(const ulonglong2*)&rhdup[k * 4];
                ulonglong2 r23 = *(const ulonglong2*)&rhdup[k * 4 + 2];
                FMA2(ag[0], r01.x, wgv);
                FMA2(ag[1], r01.y, wgv);
                FMA2(ag[2], r23.x, wgv);
                FMA2(ag[3], r23.y, wgv);
            }
#pragma unroll
            for (int b = 0; b < 4; b++)
                __stcg((double*)(gW + b * 512) + ct, __longlong_as_double(ag[b]));
        }
        __syncthreads();
        if (tid == 0) grp_arrive(bar);
        ep++;

        // ---- barrier shadow: next step's Abuf prefetch ----
        float npA = 0.f, npG = 0.f;
        if (t + 1 < SS) {
            const float* ab = Abuf + (size_t)((t + 1) * 32 + b0 + rb) * 1536;
            npA = __ldg(ab + rg * 512 + c0 + rc);
            if (tid < 128) npG = __ldg(ab + 1024 + c0 + rc);
        }

        if (tid == 0) grp_wait(bar, ep * 16);
        __syncthreads();

        // ---- read g partials + h update (owners = tid<128) ----
        if (tid < 128) {
            float s = pG;
#pragma unroll
            for (int w = 0; w < 16; w++) s += __ldcg(gR + w * 2048);
            float g = tanhf(s);
            float z = z_s[tid];
            float ho = hO[tid];
            float hn = z * ho + (1.f - z) * g;
            hO[tid] = hn;
            unsigned long long hd; PACK2(hd, hn);
            hdup[rc * 4 + rb] = hd;
            Hout[(size_t)(t * 32 + b0 + rb) * 512 + c0 + rc] = hn;
        }
        pA = npA; pG = npG;
        __syncthreads();
    }
}

// ---------------- hidden-state tail (h at t = SS-1 from Hout) ----------------
__global__ void copy_hidden_kernel(float* __restrict__ out,
                                   const float* __restrict__ H0f,
                                   const float* __restrict__ H1f) {
    int i = blockIdx.x * 256 + threadIdx.x;   // (B, L, H)
    if (i < BB * 2 * HH) {
        int b = i >> 10, rem = i & 1023;
        int l = rem >> 9, h = rem & 511;
        const float* src = l ? H1f : H0f;
        out[i] = src[(size_t)((SS - 1) * 32 + b) * 512 + h];
    }
}

// ---------------- launch ----------------
extern "C" void kernel_launch(void* const* d_in, const int* in_sizes, int n_in,
                              void* d_out, int out_size)
{
    const float* x    = (const float*)d_in[0];
    const float* h0   = (const float*)d_in[1];
    const float* W0xz = (const float*)d_in[2];
    const float* W0hz = (const float*)d_in[3];
    const float* b0z  = (const float*)d_in[4];
    const float* W0xr = (const float*)d_in[5];
    const float* W0hr = (const float*)d_in[6];
    const float* b0r  = (const float*)d_in[7];
    const float* W0xg = (const float*)d_in[8];
    const float* W0hg = (const float*)d_in[9];
    const float* b0g  = (const float*)d_in[10];
    const float* W1xz = (const float*)d_in[11];
    const float* W1hz = (const float*)d_in[12];
    const float* b1z  = (const float*)d_in[13];
    const float* W1xr = (const float*)d_in[14];
    const float* W1hr = (const float*)d_in[15];
    const float* b1r  = (const float*)d_in[16];
    const float* W1xg = (const float*)d_in[17];
    const float* W1hg = (const float*)d_in[18];
    const float* b1g  = (const float*)d_in[19];
    const float* Wy   = (const float*)d_in[20];
    const float* by   = (const float*)d_in[21];
    float* out = (float*)d_out;

    float *Abuf, *H0, *H1;
    cudaGetSymbolAddress((void**)&Abuf, g_Abuf);
    cudaGetSymbolAddress((void**)&H0,   g_H0);
    cudaGetSymbolAddress((void**)&H1,   g_H1);

    // smem: 3*16384 weights + hdup 256 + rhdup 256 + hO 128 + z 128 floats
    const size_t smem = (size_t)(3 * 16384 + 256 + 256 + 128 + 128) * sizeof(float);
    cudaFuncSetAttribute(gru_part_kernel,
                         cudaFuncAttributeMaxDynamicSharedMemorySize, (int)smem);

    dim3 gproj(512, 12);  // M=65536/128, N=1536/128

    // layer 0
    sgemm_kernel<<<gproj, 256>>>(x, 0, II, W0xz, W0xr, W0xg, b0z, b0r, b0g,
                                 512, Abuf, 0, 1536);
    reset_bar_kernel<<<1, 32>>>();
    gru_part_kernel<<<RGRID, 256, smem>>>(Abuf, W0hz, W0hr, W0hg, h0, 0, H0);

    // layer 1
    sgemm_kernel<<<gproj, 256>>>(H0, 1, HH, W1xz, W1xr, W1xg, b1z, b1r, b1g,
                                 512, Abuf, 0, 1536);
    reset_bar_kernel<<<1, 32>>>();
    gru_part_kernel<<<RGRID, 256, smem>>>(Abuf, W1hz, W1hr, W1hg, h0, 1, H1);

    // output head
    dim3 ghead(512, 1);
    sgemm_kernel<<<ghead, 256>>>(H1, 1, HH, Wy, Wy, Wy, by, by, by,
                                 128, out, 1, 0);

    if (out_size >= BB * SS * OO + BB * 2 * HH) {
        copy_hidden_kernel<<<128, 256>>>(out + BB * SS * OO, H0, H1);
    }
}